// round 15
// baseline (speedup 1.0000x reference)
#include <cuda_runtime.h>
#include <cuda_fp16.h>
#include <math.h>
#include <stdint.h>

#define Bz 32
#define Tz 128
#define Vz 16000
#define Ez 512
#define Hz 1024
#define Fz 2048
#define NBLK 64                            // persistent LSTM blocks (16 h-cols each)
#define HPS 40                             // half2-row stride for hTp (conflict-free)

// -------- scratch (static device globals; no runtime allocation) --------
__device__ float   g_pooled[Bz * Fz];
__device__ __half2 g_hTp[2][(Hz / 2) * HPS];   // transposed h ping-pong: [kp][b] fp16 pairs
__device__ float   g_xW[Bz * Tz * 4 * Hz];     // input-gate preactivations (fp32)
__device__ __half  g_hs16[Bz * Tz * Hz];       // hidden states fp16 (proj A)
__device__ __half  g_Wv16[Vz * Hz];
__device__ __half  g_embt16[Vz * Ez];
__device__ __half  g_Wih16[4 * Hz * Ez];
__device__ float   g_bihh[4 * Hz];             // b_ih + b_hh
__device__ int     g_idx[Bz * Tz];
__device__ int     g_flags[NBLK];

__device__ __forceinline__ float sigmoidf_(float x) {
    return 1.0f / (1.0f + expf(-x));
}
__device__ __forceinline__ uint32_t pack_h2(float x, float y) {
    __half2 h = __float22half2_rn(make_float2(x, y));
    return *reinterpret_cast<uint32_t*>(&h);
}
__device__ __forceinline__ void cpasync16(void* dst, const void* src) {
    uint32_t d = (uint32_t)__cvta_generic_to_shared(dst);
    asm volatile("cp.async.cg.shared.global [%0], [%1], 16;" :: "r"(d), "l"(src));
}
__device__ __forceinline__ void cpasync_commit() { asm volatile("cp.async.commit_group;"); }
__device__ __forceinline__ void cpasync_wait0()  { asm volatile("cp.async.wait_group 0;"); }
__device__ __forceinline__ void cpasync_wait1()  { asm volatile("cp.async.wait_group 1;"); }

__device__ __forceinline__ void mma_f16(float* c, const uint32_t* a, const uint32_t* b) {
    asm volatile(
        "mma.sync.aligned.m16n8k16.row.col.f32.f16.f16.f32 "
        "{%0,%1,%2,%3}, {%4,%5,%6,%7}, {%8,%9}, {%0,%1,%2,%3};"
        : "+f"(c[0]), "+f"(c[1]), "+f"(c[2]), "+f"(c[3])
        : "r"(a[0]), "r"(a[1]), "r"(a[2]), "r"(a[3]), "r"(b[0]), "r"(b[1]));
}
__device__ __forceinline__ void ldsm_x4(uint32_t& r0, uint32_t& r1, uint32_t& r2, uint32_t& r3,
                                        uint32_t addr) {
    asm volatile("ldmatrix.sync.aligned.m8n8.x4.shared.b16 {%0,%1,%2,%3}, [%4];"
                 : "=r"(r0), "=r"(r1), "=r"(r2), "=r"(r3) : "r"(addr));
}

// ---- mbarrier + bulk-copy helpers ----
__device__ __forceinline__ void mbar_init(uint32_t a, uint32_t cnt) {
    asm volatile("mbarrier.init.shared.b64 [%0], %1;" :: "r"(a), "r"(cnt) : "memory");
}
__device__ __forceinline__ void mbar_expect_tx(uint32_t a, uint32_t bytes) {
    asm volatile("mbarrier.arrive.expect_tx.shared.b64 _, [%0], %1;"
                 :: "r"(a), "r"(bytes) : "memory");
}
__device__ __forceinline__ void mbar_wait_parity(uint32_t a, uint32_t parity) {
    uint32_t done;
    asm volatile(
        "{\n\t.reg .pred p;\n\t"
        "mbarrier.try_wait.parity.acquire.cta.shared::cta.b64 p, [%1], %2;\n\t"
        "selp.b32 %0, 1, 0, p;\n\t}"
        : "=r"(done) : "r"(a), "r"(parity) : "memory");
    if (!done) {
        asm volatile(
            "{\n\t.reg .pred P1;\n\t"
            "WL_%=:\n\t"
            "mbarrier.try_wait.parity.acquire.cta.shared::cta.b64 P1, [%0], %1, 0x989680;\n\t"
            "@P1 bra.uni WD_%=;\n\t"
            "bra.uni WL_%=;\n\t"
            "WD_%=:\n\t}"
            :: "r"(a), "r"(parity) : "memory");
    }
}
__device__ __forceinline__ void bulk_g2s(uint32_t dst_smem, const void* src,
                                         uint32_t bytes, uint32_t mbar) {
    asm volatile(
        "cp.async.bulk.shared::cta.global.mbarrier::complete_tx::bytes [%0], [%1], %2, [%3];"
        :: "r"(dst_smem), "l"(src), "r"(bytes), "r"(mbar) : "memory");
}

// ==================== launch 0: fused small prep ====================
__global__ void prep_kernel(const float* __restrict__ features,
                            const int* __restrict__ reports,
                            const float* __restrict__ b_ih,
                            const float* __restrict__ b_hh) {
    int n = blockIdx.x * blockDim.x + threadIdx.x;   // 65536 threads
    if (n < Bz * Fz) {
        const float* p = features + (size_t)n * 49;
        float s = 0.f;
#pragma unroll
        for (int i = 0; i < 49; i++) s += p[i];
        g_pooled[n] = s * (1.0f / 49.0f);
    }
    if (n < Bz * Tz) {
        int t = n & (Tz - 1);
        g_idx[n] = (t == 0) ? 1 : reports[n - 1];    // START_IDX = 1
    }
    if (n < 4 * Hz) g_bihh[n] = b_ih[n] + b_hh[n];
    if (n < NBLK) g_flags[n] = 0;
}

// ==================== launch 1: fp32 -> fp16 conversion ====================
__global__ void round_all_kernel(const float4* __restrict__ Wv,
                                 const float4* __restrict__ emb,
                                 const float4* __restrict__ Wih) {
    int i = blockIdx.x * blockDim.x + threadIdx.x;
    const int n1 = Vz * Hz / 4, n2 = Vz * Ez / 4, n3 = 4 * Hz * Ez / 4;
    const float4* src;
    __half* dst;
    if (i < n1)              { src = Wv;  dst = g_Wv16;  }
    else if ((i -= n1) < n2) { src = emb; dst = g_embt16; }
    else if ((i -= n2) < n3) { src = Wih; dst = g_Wih16; }
    else return;
    float4 v = src[i];
    uint2 pk = make_uint2(pack_h2(v.x, v.y), pack_h2(v.z, v.w));
    *(uint2*)(dst + 4 * (size_t)i) = pk;
}

// ==================== fp16 GEMM (launches 2 and 4): ldmatrix + 3-stage pipeline ====
#define GROWH 40
#define GEMM_SMEM (size_t)(6 * 128 * GROWH * sizeof(__half))   // 3 stages x 2 mats

template<int MODE>
__global__ __launch_bounds__(256)
void gemm_f16_kernel(const float* __restrict__ bias, float* __restrict__ outp)
{
    extern __shared__ __half gsm[];
    __half* Asm = gsm;                        // [3][128*GROWH]
    __half* Bsm = gsm + 3 * 128 * GROWH;      // [3][128*GROWH]

    constexpr int K = (MODE == 0) ? Ez : Hz;
    constexpr int N = (MODE == 0) ? 4 * Hz : Vz;
    const __half* A  = (MODE == 0) ? g_embt16 : g_hs16;
    const __half* Bw = (MODE == 0) ? g_Wih16 : g_Wv16;
    float* C         = (MODE == 0) ? g_xW : outp;
    const float* bias_p = (MODE == 0) ? g_bihh : bias;

    int tid = threadIdx.x;
    int m0 = blockIdx.x * 128;
    int n0 = blockIdx.y * 128;

    int wid = tid >> 5, lane = tid & 31;
    int wm = (wid >> 2) * 64;
    int wn = (wid & 3) * 32;
    int gid = lane >> 2, tig = lane & 3;

    int mat = lane >> 3, lr = lane & 7;
    int rowA = wm + (mat & 1) * 8 + lr;
    int kA   = (mat >> 1) * 8;
    int rowB = wn + (mat >> 1) * 8 + lr;
    int kB   = (mat & 1) * 8;
    uint32_t asm_u32 = (uint32_t)__cvta_generic_to_shared(Asm);
    uint32_t bsm_u32 = (uint32_t)__cvta_generic_to_shared(Bsm);

    float acc[4][4][4];
#pragma unroll
    for (int i = 0; i < 4; i++)
#pragma unroll
        for (int j = 0; j < 4; j++)
#pragma unroll
            for (int q = 0; q < 4; q++) acc[i][j][q] = 0.f;

    int ldr = tid >> 2;
    int ldcH = (tid & 3) * 8;

    const __half* aRow0;
    const __half* aRow1;
    if (MODE == 0) {
        aRow0 = A + (size_t)g_idx[m0 + ldr] * K;
        aRow1 = A + (size_t)g_idx[m0 + ldr + 64] * K;
    } else {
        aRow0 = A + (size_t)(m0 + ldr) * K;
        aRow1 = aRow0 + (size_t)64 * K;
    }
    const __half* bRow0 = Bw + (size_t)(n0 + ldr) * K;
    const __half* bRow1 = bRow0 + (size_t)64 * K;

    const int NT = K / 32;

    // prologue: tiles 0 and 1
#pragma unroll
    for (int p = 0; p < 2; p++) {
        int sb = p * 128 * GROWH;
        int k0 = p * 32 + ldcH;
        cpasync16(&Asm[sb + ldr * GROWH + ldcH],        aRow0 + k0);
        cpasync16(&Asm[sb + (ldr + 64) * GROWH + ldcH], aRow1 + k0);
        cpasync16(&Bsm[sb + ldr * GROWH + ldcH],        bRow0 + k0);
        cpasync16(&Bsm[sb + (ldr + 64) * GROWH + ldcH], bRow1 + k0);
        cpasync_commit();
    }

    int buf = 0, nbuf = 2;
    for (int t = 0; t < NT; t++) {
        if (t + 1 < NT) cpasync_wait1(); else cpasync_wait0();
        __syncthreads();
        if (t + 2 < NT) {
            int sb = nbuf * 128 * GROWH;
            int k0 = (t + 2) * 32 + ldcH;
            cpasync16(&Asm[sb + ldr * GROWH + ldcH],        aRow0 + k0);
            cpasync16(&Asm[sb + (ldr + 64) * GROWH + ldcH], aRow1 + k0);
            cpasync16(&Bsm[sb + ldr * GROWH + ldcH],        bRow0 + k0);
            cpasync16(&Bsm[sb + (ldr + 64) * GROWH + ldcH], bRow1 + k0);
            cpasync_commit();
        }
        nbuf = (nbuf == 2) ? 0 : nbuf + 1;
        int cb = buf * 128 * GROWH;
        buf = (buf == 2) ? 0 : buf + 1;
#pragma unroll
        for (int ks = 0; ks < 2; ks++) {
            int kb = ks * 16;
            uint32_t a[4][4], b[4][2];
#pragma unroll
            for (int i = 0; i < 4; i++) {
                uint32_t ad = asm_u32 + 2u * (cb + (rowA + i * 16) * GROWH + kb + kA);
                ldsm_x4(a[i][0], a[i][1], a[i][2], a[i][3], ad);
            }
#pragma unroll
            for (int p = 0; p < 2; p++) {
                uint32_t ad = bsm_u32 + 2u * (cb + (rowB + p * 16) * GROWH + kb + kB);
                ldsm_x4(b[2 * p][0], b[2 * p][1], b[2 * p + 1][0], b[2 * p + 1][1], ad);
            }
#pragma unroll
            for (int i = 0; i < 4; i++)
#pragma unroll
                for (int j = 0; j < 4; j++)
                    mma_f16(acc[i][j], a[i], b[j]);
        }
    }

#pragma unroll
    for (int j = 0; j < 4; j++) {
        int col = n0 + wn + j * 8 + tig * 2;
        float2 bvv = *(const float2*)(bias_p + col);
#pragma unroll
        for (int i = 0; i < 4; i++) {
            int r = m0 + wm + i * 16 + gid;
            float2 v0 = make_float2(acc[i][j][0] + bvv.x, acc[i][j][1] + bvv.y);
            float2 v1 = make_float2(acc[i][j][2] + bvv.x, acc[i][j][3] + bvv.y);
            *(float2*)(C + (size_t)r * N + col)       = v0;
            *(float2*)(C + (size_t)(r + 8) * N + col) = v1;
        }
    }
}

// ==================== launch 3 (ncu-captured): persistent LSTM, 64 blocks ========
// Block bx owns h cols [16bx, 16bx+16) = 64 gate-rows (4 gates x 16 cols).
// Warps: nh = w>>2 (n-half, 32 rows), kq = w&3 (k-quarter, 256 k).
// W_hh B-frags in regs: Bf[16][4][2]. h exchange: 80 KB volley, 4 chunks of 20 KB,
// per-chunk mbarrier; warp kq waits chunk kq only. 4-way cross-warp reduction per half.
#define HT_BYTES ((Hz / 2) * HPS * 4)          // 81920
#define CHUNK_BYTES (HT_BYTES / 4)             // 20480
#define RED_FLOATS (8 * 32 * 36)               // 9216 floats
#define GSS 72                                 // gs row stride (floats)
#define SMEM_LSTM (size_t)(HT_BYTES + (RED_FLOATS + 32 * GSS) * 4 + 64)

__global__ __launch_bounds__(256)
void lstm_persistent(const float* __restrict__ Whh,
                     const float* __restrict__ fc_W,
                     const float* __restrict__ fc_b)
{
    extern __shared__ char smraw[];
    __half2* hsm2 = (__half2*)smraw;                            // [(Hz/2)*HPS]
    float* red = (float*)(smraw + HT_BYTES);                    // [8][32][36]
    float* gs  = (float*)(smraw + HT_BYTES + RED_FLOATS * 4);   // [32][GSS]
    uint32_t smem_base = (uint32_t)__cvta_generic_to_shared(smraw);
    uint32_t hsm_u32  = smem_base;
    uint32_t mbar_u32 = smem_base + HT_BYTES + (RED_FLOATS + 32 * GSS) * 4;  // 4 mbarriers

    int tid = threadIdx.x;
    int bx = blockIdx.x;
    int j0 = bx * 16;
    int lane = tid & 31;
    int w = tid >> 5;
    int nh = w >> 2;                   // n-half (0: rows 0..31, 1: rows 32..63)
    int kq = w & 3;                    // k-quarter (256 k each)
    int gid = lane >> 2, tig = lane & 3;
    int bb = tid >> 3, jj = tid & 7;   // elementwise: batch bb, cols jj and jj+8

    if (tid < 4) mbar_init(mbar_u32 + 8 * tid, 1);

    // ---- prologue A: W_hh B-fragments -> registers ----
    // Bf[s][nt]: n_local = nh*32 + nt*8 + gid -> grow = (n_local>>4)*Hz + j0 + (n_local&15)
    //            k = kq*256 + 16s + 2tig (b0: k,k+1 ; b1: k+8,k+9)
    uint32_t Bf[16][4][2];
#pragma unroll
    for (int s = 0; s < 16; s++) {
#pragma unroll
        for (int nt = 0; nt < 4; nt++) {
            int nl = nh * 32 + nt * 8 + gid;
            const float* wrow = Whh + (size_t)((nl >> 4) * Hz + j0 + (nl & 15)) * Hz
                                + kq * 256 + 16 * s + 2 * tig;
            float2 w0 = *(const float2*)(wrow);
            float2 w1 = *(const float2*)(wrow + 8);
            Bf[s][nt][0] = pack_h2(w0.x, w0.y);
            Bf[s][nt][1] = pack_h2(w1.x, w1.y);
        }
    }

    // ---- prologue B: init h0/c0 (warp-coop dots; 128 dots/warp) ----
    for (int oo = 0; oo < 128; oo++) {
        int o = w * 128 + oo;          // 0..1023
        int b = o & 31, r = o >> 5;    // r 0..31: r<16 -> h0 col j0+r, else c0 col j0+r-16
        int grow = (r < 16) ? (j0 + r) : (Hz + j0 + (r - 16));
        const float4* wp = (const float4*)(fc_W + (size_t)grow * Fz);
        const float4* pp = (const float4*)(g_pooled + (size_t)b * Fz);
        float4 s4 = make_float4(0.f, 0.f, 0.f, 0.f);
        for (int f = lane; f < Fz / 4; f += 32) {
            float4 wv = wp[f];
            float4 pv = pp[f];
            s4.x += wv.x * pv.x; s4.y += wv.y * pv.y;
            s4.z += wv.z * pv.z; s4.w += wv.w * pv.w;
        }
        float v = (s4.x + s4.y) + (s4.z + s4.w);
#pragma unroll
        for (int off = 16; off; off >>= 1) v += __shfl_xor_sync(0xffffffffu, v, off);
        if (lane == 0) {
            v += fc_b[grow];
            if (r < 16) {
                int k = j0 + r;
                __half* hp = (__half*)&g_hTp[0][(k >> 1) * HPS + b];
                hp[k & 1] = __float2half_rn(v);
            } else {
                gs[b * GSS + (r - 16)] = v;
            }
        }
    }
    __syncthreads();
    float c_reg0 = gs[bb * GSS + jj];
    float c_reg1 = gs[bb * GSS + jj + 8];

    // grid barrier: all h0 visible
    __threadfence();
    __syncthreads();
    if (tid == 0) atomicExch(&g_flags[bx], 1);
    if (tid < NBLK) {
        while (((volatile int*)g_flags)[tid] < 1) __nanosleep(32);
    }
    __syncthreads();

    // ---- 128 timesteps ----
    for (int t = 0; t < Tz; t++) {
        const __half2* hT_in = g_hTp[t & 1];
        __half2*       hT_out = g_hTp[(t + 1) & 1];

        size_t gbase = ((size_t)bb * Tz + t) * (4 * Hz);
        float x0[4], x1[4];
#pragma unroll
        for (int q = 0; q < 4; q++) {
            x0[q] = __ldcs(&g_xW[gbase + q * Hz + j0 + jj]);
            x1[q] = __ldcs(&g_xW[gbase + q * Hz + j0 + jj + 8]);
        }

        // stage hTp: 4 chunked bulk copies (20 KB each), per-chunk mbarrier
        if (tid == 0) {
#pragma unroll
            for (int i = 0; i < 4; i++) {
                mbar_expect_tx(mbar_u32 + 8 * i, (uint32_t)CHUNK_BYTES);
                bulk_g2s(hsm_u32 + i * CHUNK_BYTES,
                         (const char*)hT_in + i * CHUNK_BYTES,
                         CHUNK_BYTES, mbar_u32 + 8 * i);
            }
        }
        // warp waits only its k-quarter (chunk kq: kp in [128kq, 128kq+128))
        mbar_wait_parity(mbar_u32 + 8 * kq, t & 1);

        float acc[2][4][4];
#pragma unroll
        for (int mt = 0; mt < 2; mt++)
#pragma unroll
            for (int nt = 0; nt < 4; nt++)
#pragma unroll
                for (int q = 0; q < 4; q++) acc[mt][nt][q] = 0.f;

#pragma unroll
        for (int s = 0; s < 16; s++) {
            int kpb = 128 * kq + 8 * s;
            uint32_t a[2][4];
#pragma unroll
            for (int mt = 0; mt < 2; mt++) {
                int m = mt * 16 + gid;
                a[mt][0] = *(const uint32_t*)(&hsm2[(kpb + tig) * HPS + m]);
                a[mt][1] = *(const uint32_t*)(&hsm2[(kpb + tig) * HPS + m + 8]);
                a[mt][2] = *(const uint32_t*)(&hsm2[(kpb + tig + 4) * HPS + m]);
                a[mt][3] = *(const uint32_t*)(&hsm2[(kpb + tig + 4) * HPS + m + 8]);
            }
#pragma unroll
            for (int nt = 0; nt < 4; nt++) {
                mma_f16(acc[0][nt], a[0], Bf[s][nt]);
                mma_f16(acc[1][nt], a[1], Bf[s][nt]);
            }
        }

        // ---- cross-warp reduction (4-way per n-half) ----
#pragma unroll
        for (int mt = 0; mt < 2; mt++) {
#pragma unroll
            for (int nt = 0; nt < 4; nt++) {
                int row0 = mt * 16 + gid;
                int n = nt * 8 + 2 * tig;            // local col within half (0..31)
                *(float2*)(red + (w * 32 + row0) * 36 + n) =
                    make_float2(acc[mt][nt][0], acc[mt][nt][1]);
                *(float2*)(red + (w * 32 + row0 + 8) * 36 + n) =
                    make_float2(acc[mt][nt][2], acc[mt][nt][3]);
            }
        }
        __syncthreads();
        {
#pragma unroll
            for (int it = 0; it < 2; it++) {
                int item = tid + it * 256;           // 0..511
                int b = item >> 4;                   // 0..31
                int n4 = item & 15;                  // 0..15 (float4 within 64 cols)
                int hh = n4 >> 3;                    // which n-half
                int base = (n4 & 7) * 4;
                float4 sum = make_float4(0.f, 0.f, 0.f, 0.f);
#pragma unroll
                for (int q = 0; q < 4; q++) {
                    float4 v = *(const float4*)(red + ((hh * 4 + q) * 32 + b) * 36 + base);
                    sum.x += v.x; sum.y += v.y; sum.z += v.z; sum.w += v.w;
                }
                *(float4*)(gs + b * GSS + n4 * 4) = sum;
            }
        }
        __syncthreads();

        // ---- elementwise gate update (cols jj and jj+8) ----
        // gs layout: n_local = gate*16 + col_local
        {
            float gi = gs[bb * GSS +  0 + jj] + x0[0];
            float gf = gs[bb * GSS + 16 + jj] + x0[1];
            float gg = gs[bb * GSS + 32 + jj] + x0[2];
            float go = gs[bb * GSS + 48 + jj] + x0[3];
            float cn = sigmoidf_(gf) * c_reg0 + sigmoidf_(gi) * tanhf(gg);
            float hn = sigmoidf_(go) * tanhf(cn);
            c_reg0 = cn;
            __half hr = __float2half_rn(hn);
            int k = j0 + jj;
            ((__half*)&hT_out[(k >> 1) * HPS + bb])[k & 1] = hr;
            g_hs16[((size_t)bb * Tz + t) * Hz + k] = hr;
        }
        {
            float gi = gs[bb * GSS +  0 + jj + 8] + x1[0];
            float gf = gs[bb * GSS + 16 + jj + 8] + x1[1];
            float gg = gs[bb * GSS + 32 + jj + 8] + x1[2];
            float go = gs[bb * GSS + 48 + jj + 8] + x1[3];
            float cn = sigmoidf_(gf) * c_reg1 + sigmoidf_(gi) * tanhf(gg);
            float hn = sigmoidf_(go) * tanhf(cn);
            c_reg1 = cn;
            __half hr = __float2half_rn(hn);
            int k = j0 + jj + 8;
            ((__half*)&hT_out[(k >> 1) * HPS + bb])[k & 1] = hr;
            g_hs16[((size_t)bb * Tz + t) * Hz + k] = hr;
        }

        // ---- grid barrier (64 participants) ----
        __threadfence();
        __syncthreads();
        if (tid == 0) atomicExch(&g_flags[bx], t + 2);
        if (tid < NBLK) {
            while (((volatile int*)g_flags)[tid] < t + 2) __nanosleep(32);
        }
        __syncthreads();
    }
}

// ==================== launcher ====================
extern "C" void kernel_launch(void* const* d_in, const int* in_sizes, int n_in,
                              void* d_out, int out_size) {
    const float* features = (const float*)d_in[0];
    const int*   reports  = (const int*)d_in[1];
    const float* fc_W     = (const float*)d_in[2];
    const float* fc_b     = (const float*)d_in[3];
    const float* emb      = (const float*)d_in[4];
    const float* W_ih     = (const float*)d_in[5];
    const float* W_hh     = (const float*)d_in[6];
    const float* b_ih     = (const float*)d_in[7];
    const float* b_hh     = (const float*)d_in[8];
    const float* Wv       = (const float*)d_in[9];
    const float* bv       = (const float*)d_in[10];
    float* out = (float*)d_out;

    (void)in_sizes; (void)n_in; (void)out_size;

    cudaFuncSetAttribute(lstm_persistent,
                         cudaFuncAttributeMaxDynamicSharedMemorySize, (int)SMEM_LSTM);
    cudaFuncSetAttribute(gemm_f16_kernel<0>,
                         cudaFuncAttributeMaxDynamicSharedMemorySize, (int)GEMM_SMEM);
    cudaFuncSetAttribute(gemm_f16_kernel<1>,
                         cudaFuncAttributeMaxDynamicSharedMemorySize, (int)GEMM_SMEM);

    // launch 0: fused prep (pool + idx + bias + flags)
    prep_kernel<<<(Bz * Fz + 255) / 256, 256>>>(features, reports, b_ih, b_hh);

    // launch 1: fp32 -> fp16 conversion (Wv, emb, W_ih)
    {
        int n = (Vz * Hz + Vz * Ez + 4 * Hz * Ez) / 4;
        round_all_kernel<<<(n + 255) / 256, 256>>>((const float4*)Wv,
                                                   (const float4*)emb,
                                                   (const float4*)W_ih);
    }

    // launch 2: input GEMM  xW = emb[idx] @ W_ih^T + (b_ih + b_hh)
    gemm_f16_kernel<0><<<dim3(Bz * Tz / 128, 4 * Hz / 128), 256, GEMM_SMEM>>>(nullptr, nullptr);

    // launch 3 (ncu-captured): persistent LSTM (init + 128 timesteps)
    lstm_persistent<<<NBLK, 256, SMEM_LSTM>>>(W_hh, fc_W, fc_b);

    // launch 4: projection  out = hs @ Wv^T + bv
    gemm_f16_kernel<1><<<dim3(Bz * Tz / 128, Vz / 128), 256, GEMM_SMEM>>>(bv, out);
}

// round 16
// speedup vs baseline: 1.1778x; 1.1778x over previous
#include <cuda_runtime.h>
#include <cuda_fp16.h>
#include <math.h>
#include <stdint.h>

#define Bz 32
#define Tz 128
#define Vz 16000
#define Ez 512
#define Hz 1024
#define Fz 2048
#define NBLK 128
#define HPS 40                             // half2-row stride for hTp (conflict-free)

// -------- scratch (static device globals; no runtime allocation) --------
__device__ float   g_pooled[Bz * Fz];
__device__ __half2 g_hTp[2][(Hz / 2) * HPS];   // transposed h ping-pong: [kp][b] fp16 pairs
__device__ float   g_xW[Bz * Tz * 4 * Hz];     // input-gate preactivations (fp32)
__device__ __half  g_hs16[Bz * Tz * Hz];       // hidden states fp16 (proj A)
__device__ __half  g_Wv16[Vz * Hz];
__device__ __half  g_embt16[Vz * Ez];
__device__ __half  g_Wih16[4 * Hz * Ez];
__device__ float   g_bihh[4 * Hz];             // b_ih + b_hh
__device__ int     g_idx[Bz * Tz];
__device__ int     g_flags[NBLK];

__device__ __forceinline__ float sigmoidf_(float x) {
    return 1.0f / (1.0f + expf(-x));
}
__device__ __forceinline__ uint32_t pack_h2(float x, float y) {
    __half2 h = __float22half2_rn(make_float2(x, y));
    return *reinterpret_cast<uint32_t*>(&h);
}
__device__ __forceinline__ void cpasync16(void* dst, const void* src) {
    uint32_t d = (uint32_t)__cvta_generic_to_shared(dst);
    asm volatile("cp.async.cg.shared.global [%0], [%1], 16;" :: "r"(d), "l"(src));
}
__device__ __forceinline__ void cpasync_commit() { asm volatile("cp.async.commit_group;"); }
__device__ __forceinline__ void cpasync_wait0()  { asm volatile("cp.async.wait_group 0;"); }

__device__ __forceinline__ void mma_f16(float* c, const uint32_t* a, const uint32_t* b) {
    asm volatile(
        "mma.sync.aligned.m16n8k16.row.col.f32.f16.f16.f32 "
        "{%0,%1,%2,%3}, {%4,%5,%6,%7}, {%8,%9}, {%0,%1,%2,%3};"
        : "+f"(c[0]), "+f"(c[1]), "+f"(c[2]), "+f"(c[3])
        : "r"(a[0]), "r"(a[1]), "r"(a[2]), "r"(a[3]), "r"(b[0]), "r"(b[1]));
}
__device__ __forceinline__ void ldsm_x4(uint32_t& r0, uint32_t& r1, uint32_t& r2, uint32_t& r3,
                                        uint32_t addr) {
    asm volatile("ldmatrix.sync.aligned.m8n8.x4.shared.b16 {%0,%1,%2,%3}, [%4];"
                 : "=r"(r0), "=r"(r1), "=r"(r2), "=r"(r3) : "r"(addr));
}

// ---- mbarrier + bulk-copy helpers ----
__device__ __forceinline__ void mbar_init(uint32_t a, uint32_t cnt) {
    asm volatile("mbarrier.init.shared.b64 [%0], %1;" :: "r"(a), "r"(cnt) : "memory");
}
__device__ __forceinline__ void mbar_expect_tx(uint32_t a, uint32_t bytes) {
    asm volatile("mbarrier.arrive.expect_tx.shared.b64 _, [%0], %1;"
                 :: "r"(a), "r"(bytes) : "memory");
}
__device__ __forceinline__ void mbar_wait_parity(uint32_t a, uint32_t parity) {
    uint32_t done;
    asm volatile(
        "{\n\t.reg .pred p;\n\t"
        "mbarrier.try_wait.parity.acquire.cta.shared::cta.b64 p, [%1], %2;\n\t"
        "selp.b32 %0, 1, 0, p;\n\t}"
        : "=r"(done) : "r"(a), "r"(parity) : "memory");
    if (!done) {
        asm volatile(
            "{\n\t.reg .pred P1;\n\t"
            "WL_%=:\n\t"
            "mbarrier.try_wait.parity.acquire.cta.shared::cta.b64 P1, [%0], %1, 0x989680;\n\t"
            "@P1 bra.uni WD_%=;\n\t"
            "bra.uni WL_%=;\n\t"
            "WD_%=:\n\t}"
            :: "r"(a), "r"(parity) : "memory");
    }
}
__device__ __forceinline__ void bulk_g2s(uint32_t dst_smem, const void* src,
                                         uint32_t bytes, uint32_t mbar) {
    asm volatile(
        "cp.async.bulk.shared::cta.global.mbarrier::complete_tx::bytes [%0], [%1], %2, [%3];"
        :: "r"(dst_smem), "l"(src), "r"(bytes), "r"(mbar) : "memory");
}

// ==================== launch 0: fused small prep ====================
__global__ void prep_kernel(const float* __restrict__ features,
                            const int* __restrict__ reports,
                            const float* __restrict__ b_ih,
                            const float* __restrict__ b_hh) {
    int n = blockIdx.x * blockDim.x + threadIdx.x;   // 65536 threads
    if (n < Bz * Fz) {
        const float* p = features + (size_t)n * 49;
        float s = 0.f;
#pragma unroll
        for (int i = 0; i < 49; i++) s += p[i];
        g_pooled[n] = s * (1.0f / 49.0f);
    }
    if (n < Bz * Tz) {
        int t = n & (Tz - 1);
        g_idx[n] = (t == 0) ? 1 : reports[n - 1];    // START_IDX = 1
    }
    if (n < 4 * Hz) g_bihh[n] = b_ih[n] + b_hh[n];
    if (n < NBLK) g_flags[n] = 0;
}

// ==================== launch 1: fp32 -> fp16 conversion ====================
__global__ void round_all_kernel(const float4* __restrict__ Wv,
                                 const float4* __restrict__ emb,
                                 const float4* __restrict__ Wih) {
    int i = blockIdx.x * blockDim.x + threadIdx.x;
    const int n1 = Vz * Hz / 4, n2 = Vz * Ez / 4, n3 = 4 * Hz * Ez / 4;
    const float4* src;
    __half* dst;
    if (i < n1)              { src = Wv;  dst = g_Wv16;  }
    else if ((i -= n1) < n2) { src = emb; dst = g_embt16; }
    else if ((i -= n2) < n3) { src = Wih; dst = g_Wih16; }
    else return;
    float4 v = src[i];
    uint2 pk = make_uint2(pack_h2(v.x, v.y), pack_h2(v.z, v.w));
    *(uint2*)(dst + 4 * (size_t)i) = pk;
}

// ==================== fp16 tensor-core GEMM (launches 2 and 4), ldmatrix frags ====
// (R13-proven: BK=32, 2-stage, GROWH=40, single sync per tile)
#define GROWH 40
#define GEMM_SMEM (size_t)(4 * 128 * GROWH * sizeof(__half))   // 40 KB

template<int MODE>
__global__ __launch_bounds__(256)
void gemm_f16_kernel(const float* __restrict__ bias, float* __restrict__ outp)
{
    extern __shared__ __half gsm[];
    __half* Asm = gsm;                        // [2][128*GROWH]
    __half* Bsm = gsm + 2 * 128 * GROWH;      // [2][128*GROWH]

    constexpr int K = (MODE == 0) ? Ez : Hz;
    constexpr int N = (MODE == 0) ? 4 * Hz : Vz;
    const __half* A  = (MODE == 0) ? g_embt16 : g_hs16;
    const __half* Bw = (MODE == 0) ? g_Wih16 : g_Wv16;
    float* C         = (MODE == 0) ? g_xW : outp;
    const float* bias_p = (MODE == 0) ? g_bihh : bias;

    int tid = threadIdx.x;
    int m0 = blockIdx.x * 128;
    int n0 = blockIdx.y * 128;

    int wid = tid >> 5, lane = tid & 31;
    int wm = (wid >> 2) * 64;
    int wn = (wid & 3) * 32;
    int gid = lane >> 2, tig = lane & 3;

    // ldmatrix per-lane row/col offsets
    int mat = lane >> 3, lr = lane & 7;
    int rowA = wm + (mat & 1) * 8 + lr;       // + i*16
    int kA   = (mat >> 1) * 8;
    int rowB = wn + (mat >> 1) * 8 + lr;      // + p*16
    int kB   = (mat & 1) * 8;
    uint32_t asm_u32 = (uint32_t)__cvta_generic_to_shared(Asm);
    uint32_t bsm_u32 = (uint32_t)__cvta_generic_to_shared(Bsm);

    float acc[4][4][4];
#pragma unroll
    for (int i = 0; i < 4; i++)
#pragma unroll
        for (int j = 0; j < 4; j++)
#pragma unroll
            for (int q = 0; q < 4; q++) acc[i][j][q] = 0.f;

    int ldr = tid >> 2;                 // 0..63
    int ldcH = (tid & 3) * 8;           // 0,8,16,24

    const __half* aRow0;
    const __half* aRow1;
    if (MODE == 0) {
        aRow0 = A + (size_t)g_idx[m0 + ldr] * K;
        aRow1 = A + (size_t)g_idx[m0 + ldr + 64] * K;
    } else {
        aRow0 = A + (size_t)(m0 + ldr) * K;
        aRow1 = aRow0 + (size_t)64 * K;
    }
    const __half* bRow0 = Bw + (size_t)(n0 + ldr) * K;
    const __half* bRow1 = bRow0 + (size_t)64 * K;

    const int NT = K / 32;

    cpasync16(&Asm[ldr * GROWH + ldcH],        aRow0 + ldcH);
    cpasync16(&Asm[(ldr + 64) * GROWH + ldcH], aRow1 + ldcH);
    cpasync16(&Bsm[ldr * GROWH + ldcH],        bRow0 + ldcH);
    cpasync16(&Bsm[(ldr + 64) * GROWH + ldcH], bRow1 + ldcH);
    cpasync_commit();

    for (int t = 0; t < NT; t++) {
        cpasync_wait0();
        __syncthreads();
        if (t + 1 < NT) {
            int nb = ((t + 1) & 1) * 128 * GROWH;
            int k0 = (t + 1) * 32 + ldcH;
            cpasync16(&Asm[nb + ldr * GROWH + ldcH],        aRow0 + k0);
            cpasync16(&Asm[nb + (ldr + 64) * GROWH + ldcH], aRow1 + k0);
            cpasync16(&Bsm[nb + ldr * GROWH + ldcH],        bRow0 + k0);
            cpasync16(&Bsm[nb + (ldr + 64) * GROWH + ldcH], bRow1 + k0);
            cpasync_commit();
        }
        int cb = (t & 1) * 128 * GROWH;
#pragma unroll
        for (int ks = 0; ks < 2; ks++) {
            int kb = ks * 16;
            uint32_t a[4][4], b[4][2];
#pragma unroll
            for (int i = 0; i < 4; i++) {
                uint32_t ad = asm_u32 + 2u * (cb + (rowA + i * 16) * GROWH + kb + kA);
                ldsm_x4(a[i][0], a[i][1], a[i][2], a[i][3], ad);
            }
#pragma unroll
            for (int p = 0; p < 2; p++) {
                uint32_t ad = bsm_u32 + 2u * (cb + (rowB + p * 16) * GROWH + kb + kB);
                ldsm_x4(b[2 * p][0], b[2 * p][1], b[2 * p + 1][0], b[2 * p + 1][1], ad);
            }
#pragma unroll
            for (int i = 0; i < 4; i++)
#pragma unroll
                for (int j = 0; j < 4; j++)
                    mma_f16(acc[i][j], a[i], b[j]);
        }
    }

#pragma unroll
    for (int j = 0; j < 4; j++) {
        int col = n0 + wn + j * 8 + tig * 2;
        float2 bvv = *(const float2*)(bias_p + col);
#pragma unroll
        for (int i = 0; i < 4; i++) {
            int r = m0 + wm + i * 16 + gid;
            float2 v0 = make_float2(acc[i][j][0] + bvv.x, acc[i][j][1] + bvv.y);
            float2 v1 = make_float2(acc[i][j][2] + bvv.x, acc[i][j][3] + bvv.y);
            *(float2*)(C + (size_t)r * N + col)       = v0;
            *(float2*)(C + (size_t)(r + 8) * N + col) = v1;
        }
    }
}

// ==================== launch 3 (ncu-captured): persistent LSTM (R13 + reorders) ====
// 128 blocks x 256 thr. Block bx owns h cols [8bx, 8bx+8) = 32 gate-rows.
// W_hh B-frags in regs. h exchange: 80 KB volley, 8 chunks / 8 mbarriers.
// R15 changes: (1) DMA issued at the top of the step (before xW prefetch);
// (2) split-phase grid barrier — arrive right after hT_out visible, g_hs16
//     store hidden between arrive and wait.
#define HT_BYTES ((Hz / 2) * HPS * 4)          // 81920
#define CHUNK_BYTES (HT_BYTES / 8)             // 10240
#define SMEM_LSTM (size_t)(HT_BYTES + (9216 + 1152) * 4 + 64)

__global__ __launch_bounds__(256)
void lstm_persistent(const float* __restrict__ Whh,
                     const float* __restrict__ fc_W,
                     const float* __restrict__ fc_b)
{
    extern __shared__ char smraw[];
    __half2* hsm2 = (__half2*)smraw;                       // [(Hz/2)*HPS]
    float* red = (float*)(smraw + HT_BYTES);               // [8][32][36]
    float* gs  = (float*)(smraw + HT_BYTES + 9216 * 4);    // [32][36]
    uint32_t smem_base = (uint32_t)__cvta_generic_to_shared(smraw);
    uint32_t hsm_u32  = smem_base;
    uint32_t mbar_u32 = smem_base + HT_BYTES + (9216 + 1152) * 4;  // 8 mbarriers

    int tid = threadIdx.x;
    int bx = blockIdx.x;
    int j0 = bx * 8;
    int lane = tid & 31;
    int w = tid >> 5;
    int gid = lane >> 2, tig = lane & 3;
    int bb = tid >> 3, jj = tid & 7;

    if (tid < 8) mbar_init(mbar_u32 + 8 * tid, 1);

    // ---- prologue A: W_hh B-fragments -> registers (fp16 pairs) ----
    uint32_t Bf[8][4][2];
#pragma unroll
    for (int s = 0; s < 8; s++) {
#pragma unroll
        for (int nt = 0; nt < 4; nt++) {
            const float* wrow = Whh + (size_t)(nt * Hz + j0 + gid) * Hz + 128 * w + 16 * s + 2 * tig;
            float2 w0 = *(const float2*)(wrow);
            float2 w1 = *(const float2*)(wrow + 8);
            Bf[s][nt][0] = pack_h2(w0.x, w0.y);
            Bf[s][nt][1] = pack_h2(w1.x, w1.y);
        }
    }

    // ---- prologue B: init h0/c0 for this block's columns (warp-coop dots) ----
    for (int oo = 0; oo < 64; oo++) {
        int o = w * 64 + oo;
        int b = o & 31, r = o >> 5;
        int grow = (r < 8) ? (j0 + r) : (Hz + j0 + (r - 8));
        const float4* wp = (const float4*)(fc_W + (size_t)grow * Fz);
        const float4* pp = (const float4*)(g_pooled + (size_t)b * Fz);
        float4 s4 = make_float4(0.f, 0.f, 0.f, 0.f);
        for (int f = lane; f < Fz / 4; f += 32) {
            float4 wv = wp[f];
            float4 pv = pp[f];
            s4.x += wv.x * pv.x; s4.y += wv.y * pv.y;
            s4.z += wv.z * pv.z; s4.w += wv.w * pv.w;
        }
        float v = (s4.x + s4.y) + (s4.z + s4.w);
#pragma unroll
        for (int off = 16; off; off >>= 1) v += __shfl_xor_sync(0xffffffffu, v, off);
        if (lane == 0) {
            v += fc_b[grow];
            if (r < 8) {
                int k = j0 + r;
                __half* hp = (__half*)&g_hTp[0][(k >> 1) * HPS + b];
                hp[k & 1] = __float2half_rn(v);
            } else {
                gs[b * 36 + (r - 8)] = v;
            }
        }
    }
    __syncthreads();
    float c_reg = gs[bb * 36 + jj];

    // grid barrier: all h0 visible
    __threadfence();
    __syncthreads();
    if (tid == 0) atomicExch(&g_flags[bx], 1);
    if (tid < NBLK) {
        while (((volatile int*)g_flags)[tid] < 1) __nanosleep(32);
    }
    __syncthreads();

    // ---- 128 timesteps ----
    for (int t = 0; t < Tz; t++) {
        const __half2* hT_in = g_hTp[t & 1];
        __half2*       hT_out = g_hTp[(t + 1) & 1];

        // (1) DMA first: 8 chunked bulk copies (10 KB each), per-chunk mbarrier
        if (tid == 0) {
#pragma unroll
            for (int i = 0; i < 8; i++) {
                mbar_expect_tx(mbar_u32 + 8 * i, (uint32_t)CHUNK_BYTES);
                bulk_g2s(hsm_u32 + i * CHUNK_BYTES,
                         (const char*)hT_in + i * CHUNK_BYTES,
                         CHUNK_BYTES, mbar_u32 + 8 * i);
            }
        }

        // xW prefetch overlaps the DMA
        size_t gbase = ((size_t)bb * Tz + t) * (4 * Hz);
        float xi = __ldcs(&g_xW[gbase + 0 * Hz + j0 + jj]);
        float xf = __ldcs(&g_xW[gbase + 1 * Hz + j0 + jj]);
        float xg = __ldcs(&g_xW[gbase + 2 * Hz + j0 + jj]);
        float xo = __ldcs(&g_xW[gbase + 3 * Hz + j0 + jj]);

        // warp w waits only for its own k-slice (chunk w: kp in [64w, 64w+64))
        mbar_wait_parity(mbar_u32 + 8 * w, t & 1);

        float acc[2][4][4];
#pragma unroll
        for (int mt = 0; mt < 2; mt++)
#pragma unroll
            for (int nt = 0; nt < 4; nt++)
#pragma unroll
                for (int q = 0; q < 4; q++) acc[mt][nt][q] = 0.f;

#pragma unroll
        for (int s = 0; s < 8; s++) {
            int kpb = 64 * w + 8 * s;
            uint32_t a[2][4];
#pragma unroll
            for (int mt = 0; mt < 2; mt++) {
                int m = mt * 16 + gid;
                a[mt][0] = *(const uint32_t*)(&hsm2[(kpb + tig) * HPS + m]);
                a[mt][1] = *(const uint32_t*)(&hsm2[(kpb + tig) * HPS + m + 8]);
                a[mt][2] = *(const uint32_t*)(&hsm2[(kpb + tig + 4) * HPS + m]);
                a[mt][3] = *(const uint32_t*)(&hsm2[(kpb + tig + 4) * HPS + m + 8]);
            }
#pragma unroll
            for (int nt = 0; nt < 4; nt++) {
                mma_f16(acc[0][nt], a[0], Bf[s][nt]);
                mma_f16(acc[1][nt], a[1], Bf[s][nt]);
            }
        }

        // ---- cross-warp reduction (disjoint warp regions; prior reads fenced
        //      by the grid barrier's syncs -> no pre-sync needed) ----
#pragma unroll
        for (int mt = 0; mt < 2; mt++) {
#pragma unroll
            for (int nt = 0; nt < 4; nt++) {
                int row0 = mt * 16 + gid;
                int n = nt * 8 + 2 * tig;
                *(float2*)(red + (w * 32 + row0) * 36 + n) =
                    make_float2(acc[mt][nt][0], acc[mt][nt][1]);
                *(float2*)(red + (w * 32 + row0 + 8) * 36 + n) =
                    make_float2(acc[mt][nt][2], acc[mt][nt][3]);
            }
        }
        __syncthreads();
        {
            int b = tid >> 3, n4 = (tid & 7) * 4;
            float4 sum = make_float4(0.f, 0.f, 0.f, 0.f);
#pragma unroll
            for (int ww = 0; ww < 8; ww++) {
                float4 v = *(const float4*)(red + (ww * 32 + b) * 36 + n4);
                sum.x += v.x; sum.y += v.y; sum.z += v.z; sum.w += v.w;
            }
            *(float4*)(gs + b * 36 + n4) = sum;
        }
        __syncthreads();

        // ---- elementwise gate update ----
        float gi = gs[bb * 36 +  0 + jj] + xi;
        float gf = gs[bb * 36 +  8 + jj] + xf;
        float gg = gs[bb * 36 + 16 + jj] + xg;
        float go = gs[bb * 36 + 24 + jj] + xo;

        float cn = sigmoidf_(gf) * c_reg + sigmoidf_(gi) * tanhf(gg);
        float hn = sigmoidf_(go) * tanhf(cn);
        c_reg = cn;
        __half hr16 = __float2half_rn(hn);
        int k = j0 + jj;
        ((__half*)&hT_out[(k >> 1) * HPS + bb])[k & 1] = hr16;

        // (2) split-phase grid barrier: arrive as soon as hT_out is visible,
        //     hide the g_hs16 store inside the wait window.
        __threadfence();
        __syncthreads();
        if (tid == 0) atomicExch(&g_flags[bx], t + 2);

        g_hs16[((size_t)bb * Tz + t) * Hz + k] = hr16;   // no cross-block reader

        if (tid < NBLK) {
            while (((volatile int*)g_flags)[tid] < t + 2) __nanosleep(32);
        }
        __syncthreads();
    }
}

// ==================== launcher ====================
extern "C" void kernel_launch(void* const* d_in, const int* in_sizes, int n_in,
                              void* d_out, int out_size) {
    const float* features = (const float*)d_in[0];
    const int*   reports  = (const int*)d_in[1];
    const float* fc_W     = (const float*)d_in[2];
    const float* fc_b     = (const float*)d_in[3];
    const float* emb      = (const float*)d_in[4];
    const float* W_ih     = (const float*)d_in[5];
    const float* W_hh     = (const float*)d_in[6];
    const float* b_ih     = (const float*)d_in[7];
    const float* b_hh     = (const float*)d_in[8];
    const float* Wv       = (const float*)d_in[9];
    const float* bv       = (const float*)d_in[10];
    float* out = (float*)d_out;

    (void)in_sizes; (void)n_in; (void)out_size;

    cudaFuncSetAttribute(lstm_persistent,
                         cudaFuncAttributeMaxDynamicSharedMemorySize, (int)SMEM_LSTM);
    cudaFuncSetAttribute(gemm_f16_kernel<0>,
                         cudaFuncAttributeMaxDynamicSharedMemorySize, (int)GEMM_SMEM);
    cudaFuncSetAttribute(gemm_f16_kernel<1>,
                         cudaFuncAttributeMaxDynamicSharedMemorySize, (int)GEMM_SMEM);

    // launch 0: fused prep (pool + idx + bias + flags)
    prep_kernel<<<(Bz * Fz + 255) / 256, 256>>>(features, reports, b_ih, b_hh);

    // launch 1: fp32 -> fp16 conversion (Wv, emb, W_ih)
    {
        int n = (Vz * Hz + Vz * Ez + 4 * Hz * Ez) / 4;
        round_all_kernel<<<(n + 255) / 256, 256>>>((const float4*)Wv,
                                                   (const float4*)emb,
                                                   (const float4*)W_ih);
    }

    // launch 2: input GEMM  xW = emb[idx] @ W_ih^T + (b_ih + b_hh)
    gemm_f16_kernel<0><<<dim3(Bz * Tz / 128, 4 * Hz / 128), 256, GEMM_SMEM>>>(nullptr, nullptr);

    // launch 3 (ncu-captured): persistent LSTM (init + 128 timesteps)
    lstm_persistent<<<NBLK, 256, SMEM_LSTM>>>(W_hh, fc_W, fc_b);

    // launch 4: projection  out = hs @ Wv^T + bv
    gemm_f16_kernel<1><<<dim3(Bz * Tz / 128, Vz / 128), 256, GEMM_SMEM>>>(bv, out);
}